// round 8
// baseline (speedup 1.0000x reference)
#include <cuda_runtime.h>
#include <cuda_bf16.h>
#include <mma.h>
#include <cstdint>

using namespace nvcuda;

// ---------------- scratch (device globals; no allocation allowed) ----------------
__device__ float g_Tu[(size_t)500000 * 128];            // user table  (256 MB)
__device__ float g_Ti[(size_t)100000 * 128];            // item table  (51 MB)
__device__ unsigned short g_Bh[3 * 8192];               // B-hi row-major [k][n] per block
__device__ unsigned short g_Bl[3 * 8192];               // B-lo
__device__ int   g_is64;                                // adj dtype flag
__device__ int   g_swap;                                // adjA/adjB swap flag

// ---------------- helpers ----------------
__device__ __forceinline__ void pf_l2(const void* p) {
    asm volatile("prefetch.global.L2 [%0];" :: "l"(p));
}
// split fp32 pair -> bf16x2 hi + bf16x2 lo (residual)
__device__ __forceinline__ void split2(float x, float y, uint32_t& hi, uint32_t& lo) {
    uint32_t h;
    asm("cvt.rn.bf16x2.f32 %0, %1, %2;" : "=r"(h) : "f"(y), "f"(x));
    float hx = __uint_as_float(h << 16);
    float hy = __uint_as_float(h & 0xFFFF0000u);
    float lx = x - hx, ly = y - hy;
    asm("cvt.rn.bf16x2.f32 %0, %1, %2;" : "=r"(lo) : "f"(ly), "f"(lx));
    hi = h;
}

// ---------------- threefry2x32 core ----------------
__device__ __forceinline__ unsigned rotl32(unsigned x, int d) {
    return (x << d) | (x >> (32 - d));
}

__device__ void threefry2x32(unsigned k0, unsigned k1, unsigned& x0, unsigned& x1) {
    unsigned k2 = k0 ^ k1 ^ 0x1BD11BDAu;
    x0 += k0; x1 += k1;
    const int R0[4] = {13, 15, 26, 6};
    const int R1[4] = {17, 29, 16, 24};
#pragma unroll
    for (int i = 0; i < 4; i++) { x0 += x1; x1 = rotl32(x1, R0[i]); x1 ^= x0; }
    x0 += k1; x1 += k2 + 1u;
#pragma unroll
    for (int i = 0; i < 4; i++) { x0 += x1; x1 = rotl32(x1, R1[i]); x1 ^= x0; }
    x0 += k2; x1 += k0 + 2u;
#pragma unroll
    for (int i = 0; i < 4; i++) { x0 += x1; x1 = rotl32(x1, R0[i]); x1 ^= x0; }
    x0 += k0; x1 += k1 + 3u;
#pragma unroll
    for (int i = 0; i < 4; i++) { x0 += x1; x1 = rotl32(x1, R1[i]); x1 ^= x0; }
    x0 += k1; x1 += k2 + 4u;
#pragma unroll
    for (int i = 0; i < 4; i++) { x0 += x1; x1 = rotl32(x1, R0[i]); x1 ^= x0; }
    x0 += k2; x1 += k0 + 5u;
}

// ---------------- K0: jax partitionable threefry -> bf16-split B images ----------
// Blocks: 0 = review (identity), 1 = user (seed 42), 2 = item (seed 43).
// Image layout: row-major [k=0..63][n=0..127] bf16 of Wp[k][n] = W[src[k]][n].
__global__ void k_build_wp(const float* __restrict__ W,
                           const void* __restrict__ adjA) {
    __shared__ unsigned bits[2][64];
    __shared__ unsigned subk[2][2];
    __shared__ int src[192];
    const int t = threadIdx.x;
    const int s = (t < 128) ? (t >> 6) : -1;   // seed group: 0->42, 1->43
    const int i = t & 63;

    if (t < 192) src[t] = t;                   // review block stays identity

    if (t < 2) {                               // foldlike split: subkey = TF(key,(0,1))
        unsigned x0 = 0u, x1 = 1u;
        threefry2x32(0u, 42u + (unsigned)t, x0, x1);
        subk[t][0] = x0; subk[t][1] = x1;
    }
    if (t == 128) {  // int64 vs int32 probe: odd int32 slots all zero => int64
        const int* p = (const int*)adjA;
        int all0 = 1;
        for (int j = 1; j < 128; j += 2) all0 &= (p[j] == 0);
        g_is64 = all0;
    }
    __syncthreads();
    if (t == 129) {  // adjA has values >= 100000 => adjA is adj_u (no swap)
        int big = 0;
        if (g_is64) {
            const long long* a = (const long long*)adjA;
            for (int j = 0; j < 4096; j++) big |= (a[j] >= 100000);
        } else {
            const int* a = (const int*)adjA;
            for (int j = 0; j < 4096; j++) big |= (a[j] >= 100000);
        }
        g_swap = !big;
    }

    if (s >= 0) {   // partitionable random_bits: counter (0, i), output x0^x1
        unsigned x0 = 0u, x1 = (unsigned)i;
        threefry2x32(subk[s][0], subk[s][1], x0, x1);
        bits[s][i] = x0 ^ x1;
    }
    __syncthreads();

    if (s >= 0) {   // stable rank; Wp[block+i] = W[block+rank_i]
        unsigned kv = bits[s][i];
        int r = 0;
        for (int j = 0; j < 64; j++) {
            unsigned kj = bits[s][j];
            r += (kj < kv) || (kj == kv && j < i);
        }
        src[(s + 1) * 64 + i] = (s + 1) * 64 + r;
    }
    __syncthreads();

    // emit bf16-split B images, row-major [k][n]
    for (int idx = t; idx < 3 * 8192; idx += blockDim.x) {
        int b = idx >> 13;
        int r = idx & 8191;
        int k = r >> 7;               // 0..63
        int n = r & 127;              // 0..127
        float v = W[src[b * 64 + k] * 128 + n];
        unsigned short h;
        asm("cvt.rn.bf16.f32 %0, %1;" : "=h"(h) : "f"(v));
        float hf = __uint_as_float(((unsigned)h) << 16);
        float lres = v - hf;
        unsigned short lo;
        asm("cvt.rn.bf16.f32 %0, %1;" : "=h"(lo) : "f"(lres));
        g_Bh[idx] = h;
        g_Bl[idx] = lo;
    }
}

// ---------------- wmma GEMM: C[128,128] = A[128,64] @ B[64,128] (+ epilogue) -----
// MODE 0: A=item  -> g_Ti (B blk 2)   MODE 1: A=user -> g_Tu (B blk 1)
// MODE 2: A=review-> out = relu(. + g_Tu[adj_u] + g_Ti[adj_i])  (B blk 0)
// 256 thr (8 warps). Warp w: rows (w&3)*32, cols (w>>2)*64. bf16 split:
// D = AhBh + AhBl + AlBh, fp32 accumulate.
constexpr int LDA = 72;    // smem ld for A (bf16 elems)
constexpr int LDB = 136;   // smem ld for B
constexpr int OF_AH = 0;
constexpr int OF_AL = OF_AH + 128 * LDA * 2;          // 18432
constexpr int OF_BH = OF_AL + 128 * LDA * 2;          // 36864
constexpr int OF_BL = OF_BH + 64 * LDB * 2;           // 54272
constexpr int OF_IDX = OF_BL + 64 * LDB * 2;          // 71680
constexpr int SMEM_DYN = OF_IDX + 2 * 128 * 4;        // 72704

template <int MODE>
__global__ __launch_bounds__(256, 2)
void k_gemm_wmma(const float* __restrict__ A, int M, float* __restrict__ Cout,
                 const void* __restrict__ adjA, const void* __restrict__ adjB) {
    constexpr int BLK = (MODE == 2) ? 0 : (MODE == 1 ? 1 : 2);

    extern __shared__ __align__(16) char smem[];
    __nv_bfloat16* sAh = (__nv_bfloat16*)(smem + OF_AH);
    __nv_bfloat16* sAl = (__nv_bfloat16*)(smem + OF_AL);
    __nv_bfloat16* sBh = (__nv_bfloat16*)(smem + OF_BH);
    __nv_bfloat16* sBl = (__nv_bfloat16*)(smem + OF_BL);
    int* s_iu = (int*)(smem + OF_IDX);
    int* s_ii = s_iu + 128;

    const int t = threadIdx.x;
    const int w = t >> 5;
    const int row0 = blockIdx.x * 128;
    const int wr = (w & 3) * 32;     // warp row base
    const int wc = (w >> 2) * 64;    // warp col base

    // ---- copy B images ----
    {
        const uint4* bh4 = (const uint4*)(g_Bh + BLK * 8192);
        const uint4* bl4 = (const uint4*)(g_Bl + BLK * 8192);
#pragma unroll
        for (int it = 0; it < 4; it++) {
            int q = it * 256 + t;           // 0..1023 uint4 tasks (8 bf16 each)
            int k = q >> 4, f = q & 15;
            *(uint4*)((char*)sBh + k * (LDB * 2) + f * 16) = bh4[q];
            *(uint4*)((char*)sBl + k * (LDB * 2) + f * 16) = bl4[q];
        }
    }

    // ---- adjacency indices + L2 prefetch (MODE 2) ----
    if (MODE == 2 && t < 128) {
        const void* aU = g_swap ? adjB : adjA;
        const void* aI = g_swap ? adjA : adjB;
        int gr = min(row0 + t, M - 1);
        int iu, ii;
        if (g_is64) {
            iu = (int)((const long long*)aU)[gr];
            ii = (int)((const long long*)aI)[gr];
        } else {
            iu = ((const int*)aU)[gr];
            ii = ((const int*)aI)[gr];
        }
        s_iu[t] = iu; s_ii[t] = ii;
        const char* pu = (const char*)(g_Tu + ((size_t)iu << 7));
        const char* pi = (const char*)(g_Ti + ((size_t)ii << 7));
#pragma unroll
        for (int l = 0; l < 4; l++) { pf_l2(pu + l * 128); pf_l2(pi + l * 128); }
    }

    // ---- load + split A ----
    {
        const float4* A4 = (const float4*)A;
#pragma unroll
        for (int it = 0; it < 8; it++) {
            int q = it * 256 + t;            // 0..2047 float4 tasks
            int row = q >> 4, f = q & 15;    // 16 float4 per row (64 floats)
            int gr = min(row0 + row, M - 1);
            float4 v = A4[(size_t)gr * 16 + f];
            uint32_t h0, l0, h1, l1;
            split2(v.x, v.y, h0, l0);
            split2(v.z, v.w, h1, l1);
            *(uint2*)((char*)sAh + row * (LDA * 2) + f * 8) = make_uint2(h0, h1);
            *(uint2*)((char*)sAl + row * (LDA * 2) + f * 8) = make_uint2(l0, l1);
        }
    }
    __syncthreads();

    // ---- wmma compute: warp tile 32x64 = 2x4 frags ----
    wmma::fragment<wmma::accumulator, 16, 16, 16, float> acc[2][4];
#pragma unroll
    for (int i = 0; i < 2; i++)
#pragma unroll
        for (int c = 0; c < 4; c++) wmma::fill_fragment(acc[i][c], 0.0f);

#pragma unroll
    for (int kt = 0; kt < 4; kt++) {
        wmma::fragment<wmma::matrix_a, 16, 16, 16, __nv_bfloat16, wmma::row_major> ah[2], al[2];
#pragma unroll
        for (int i = 0; i < 2; i++) {
            wmma::load_matrix_sync(ah[i], sAh + (wr + i * 16) * LDA + kt * 16, LDA);
            wmma::load_matrix_sync(al[i], sAl + (wr + i * 16) * LDA + kt * 16, LDA);
        }
#pragma unroll
        for (int c = 0; c < 4; c++) {
            wmma::fragment<wmma::matrix_b, 16, 16, 16, __nv_bfloat16, wmma::row_major> bh, bl;
            wmma::load_matrix_sync(bh, sBh + (kt * 16) * LDB + wc + c * 16, LDB);
            wmma::load_matrix_sync(bl, sBl + (kt * 16) * LDB + wc + c * 16, LDB);
#pragma unroll
            for (int i = 0; i < 2; i++) {
                wmma::mma_sync(acc[i][c], ah[i], bh, acc[i][c]);
                wmma::mma_sync(acc[i][c], ah[i], bl, acc[i][c]);
                wmma::mma_sync(acc[i][c], al[i], bh, acc[i][c]);
            }
        }
    }

    // ---- stash C into smem (reuse A/B region; 64 KB < OF_IDX) ----
    __syncthreads();
    float* sC = (float*)smem;
#pragma unroll
    for (int i = 0; i < 2; i++)
#pragma unroll
        for (int c = 0; c < 4; c++)
            wmma::store_matrix_sync(sC + (wr + i * 16) * 128 + wc + c * 16,
                                    acc[i][c], 128, wmma::mem_row_major);
    __syncthreads();

    // ---- epilogue: thread handles half a row (64 cols) ----
    {
        int row = t >> 1;
        int ch = (t & 1) * 64;
        int gr = row0 + row;
        if (gr < M) {
            const float4* cs = (const float4*)(sC + row * 128 + ch);
            if (MODE == 2) {
                int iu = s_iu[row], ii = s_ii[row];
                const float4* tu = (const float4*)(g_Tu + ((size_t)iu << 7) + ch);
                const float4* ti = (const float4*)(g_Ti + ((size_t)ii << 7) + ch);
                float4* dst = (float4*)(Cout + ((size_t)gr << 7) + ch);
#pragma unroll
                for (int j = 0; j < 16; j++) {
                    float4 p = cs[j], u = tu[j], v = ti[j], o;
                    o.x = fmaxf(p.x + u.x + v.x, 0.f);
                    o.y = fmaxf(p.y + u.y + v.y, 0.f);
                    o.z = fmaxf(p.z + u.z + v.z, 0.f);
                    o.w = fmaxf(p.w + u.w + v.w, 0.f);
                    dst[j] = o;
                }
            } else {
                float* T = (MODE == 0) ? g_Ti : g_Tu;
                float4* dst = (float4*)(T + ((size_t)gr << 7) + ch);
#pragma unroll
                for (int j = 0; j < 16; j++) dst[j] = cs[j];
            }
        }
    }
}

// ---------------- launch ----------------
extern "C" void kernel_launch(void* const* d_in, const int* in_sizes, int n_in,
                              void* d_out, int out_size) {
    // classify inputs by element count (robust to metadata ordering)
    const float *review = nullptr, *user = nullptr, *item = nullptr, *W = nullptr;
    const void *adjA = nullptr, *adjB = nullptr;
    int n_r = 1000000, n_u = 500000, n_i = 100000;
    for (int k = 0; k < n_in; k++) {
        long long sz = in_sizes[k];
        if (sz == 64000000)      { review = (const float*)d_in[k]; n_r = (int)(sz / 64); }
        else if (sz == 32000000) { user   = (const float*)d_in[k]; n_u = (int)(sz / 64); }
        else if (sz == 6400000)  { item   = (const float*)d_in[k]; n_i = (int)(sz / 64); }
        else if (sz == 24576)    { W      = (const float*)d_in[k]; }
        else if (!adjA)          { adjA   = d_in[k]; }
        else                     { adjB   = d_in[k]; }
    }
    if (!review || !user || !item || !W || !adjA || !adjB) {
        review = (const float*)d_in[0]; user = (const float*)d_in[1];
        item   = (const float*)d_in[2]; W    = (const float*)d_in[3];
        adjA   = d_in[4];               adjB = d_in[5];
        n_r = in_sizes[0] / 64; n_u = in_sizes[1] / 64; n_i = in_sizes[2] / 64;
    }
    float* out = (float*)d_out;

    cudaFuncSetAttribute(k_gemm_wmma<0>, cudaFuncAttributeMaxDynamicSharedMemorySize, SMEM_DYN);
    cudaFuncSetAttribute(k_gemm_wmma<1>, cudaFuncAttributeMaxDynamicSharedMemorySize, SMEM_DYN);
    cudaFuncSetAttribute(k_gemm_wmma<2>, cudaFuncAttributeMaxDynamicSharedMemorySize, SMEM_DYN);

    k_build_wp<<<1, 256>>>(W, adjA);
    k_gemm_wmma<0><<<(n_i + 127) / 128, 256, SMEM_DYN>>>(item,   n_i, nullptr, nullptr, nullptr);
    k_gemm_wmma<1><<<(n_u + 127) / 128, 256, SMEM_DYN>>>(user,   n_u, nullptr, nullptr, nullptr);
    k_gemm_wmma<2><<<(n_r + 127) / 128, 256, SMEM_DYN>>>(review, n_r, out,     adjA,    adjB);
}